// round 9
// baseline (speedup 1.0000x reference)
#include <cuda_runtime.h>
#include <cuda_bf16.h>
#include <math.h>
#include <stdint.h>

#define BB 512
#define DD 512
#define CC 100000
#define SCALE 64.0f

#define MBT 128          // batch tile
#define NBT 256          // class tile
#define KC  64           // K chunk (128 bytes bf16)
#define NCH (DD / KC)    // 8 chunks

// ---------------- device scratch ----------------
__device__ float          g_xn[BB * DD];          // normalized x fp32 (exact label logit)
__device__ __nv_bfloat16  g_xbf[BB * DD];         // normalized x bf16
__device__ __nv_bfloat16  g_wbf[(size_t)CC * DD]; // W * (64/||w||) bf16
__device__ float          g_wscale[CC];
__device__ float          g_expsum[BB];
__device__ float          g_nll[BB];
__device__ int            g_is64;

// ---------------- PTX helpers (baseline compute_103-safe only) --------------
__device__ __forceinline__ uint32_t smem_u32(const void* p) {
    uint32_t a;
    asm("{ .reg .u64 t; cvta.to.shared.u64 t, %1; cvt.u32.u64 %0, t; }" : "=r"(a) : "l"(p));
    return a;
}
#define CP_ASYNC16(dst, src) \
    asm volatile("cp.async.cg.shared.global [%0], [%1], 16;" :: "r"(dst), "l"(src) : "memory")
#define CP_COMMIT() asm volatile("cp.async.commit_group;" ::: "memory")
#define CP_WAIT(n)  asm volatile("cp.async.wait_group %0;" :: "n"(n) : "memory")

#define LDSM4(r, addr) \
    asm volatile("ldmatrix.sync.aligned.m8n8.x4.shared.b16 {%0,%1,%2,%3}, [%4];" \
        : "=r"((r)[0]), "=r"((r)[1]), "=r"((r)[2]), "=r"((r)[3]) : "r"(addr))

#define MMA16816(d, a, b0v, b1v) \
    asm volatile("mma.sync.aligned.m16n8k16.row.col.f32.bf16.bf16.f32 " \
        "{%0,%1,%2,%3}, {%4,%5,%6,%7}, {%8,%9}, {%0,%1,%2,%3};" \
        : "+f"((d)[0]), "+f"((d)[1]), "+f"((d)[2]), "+f"((d)[3]) \
        : "r"((a)[0]), "r"((a)[1]), "r"((a)[2]), "r"((a)[3]), "r"(b0v), "r"(b1v))

// ---------------- label dtype probe ----------------
__global__ void k_probe(const int* __restrict__ lab) {
    __shared__ int s_any;
    if (threadIdx.x == 0) s_any = 0;
    __syncthreads();
    if (lab[2 * threadIdx.x + 1] != 0) atomicOr(&s_any, 1);
    __syncthreads();
    if (threadIdx.x == 0) g_is64 = (s_any == 0) ? 1 : 0;
}

// ---------------- x normalize: fp32 + bf16 outputs, zero expsum -------------
__global__ void k_norm_x(const float* __restrict__ x) {
    __shared__ float s_part[4];
    __shared__ float s_inv;
    const int m = blockIdx.x;
    const int t = threadIdx.x;                 // 128 threads
    float4 v = ((const float4*)x)[m * 128 + t];
    float ss = v.x * v.x + v.y * v.y + v.z * v.z + v.w * v.w;
    #pragma unroll
    for (int o = 16; o > 0; o >>= 1) ss += __shfl_xor_sync(0xffffffffu, ss, o);
    if ((t & 31) == 0) s_part[t >> 5] = ss;
    __syncthreads();
    if (t == 0) {
        float tot = s_part[0] + s_part[1] + s_part[2] + s_part[3];
        s_inv = 1.0f / fmaxf(sqrtf(tot), 1e-12f);
        g_expsum[m] = 0.0f;                    // re-zeroed every graph replay
    }
    __syncthreads();
    const float inv = s_inv;
    float4 o4 = make_float4(v.x * inv, v.y * inv, v.z * inv, v.w * inv);
    ((float4*)g_xn)[m * 128 + t] = o4;
    __nv_bfloat162 h0 = __floats2bfloat162_rn(o4.x, o4.y);
    __nv_bfloat162 h1 = __floats2bfloat162_rn(o4.z, o4.w);
    uint2 u;
    u.x = *(uint32_t*)&h0; u.y = *(uint32_t*)&h1;
    *(uint2*)(g_xbf + m * DD + t * 4) = u;
}

// ---------------- W norms + scaled bf16 convert (one warp per row) ----------
__global__ void k_norm_w(const float* __restrict__ w) {
    const int c = blockIdx.x * 8 + (threadIdx.x >> 5);
    const int lane = threadIdx.x & 31;
    const float4* w4 = (const float4*)(w + (size_t)c * DD);
    float4 v[4];
    float ss = 0.0f;
    #pragma unroll
    for (int q = 0; q < 4; q++) {
        v[q] = w4[q * 32 + lane];
        ss += v[q].x * v[q].x + v[q].y * v[q].y + v[q].z * v[q].z + v[q].w * v[q].w;
    }
    #pragma unroll
    for (int o = 16; o > 0; o >>= 1) ss += __shfl_xor_sync(0xffffffffu, ss, o);
    const float sc = SCALE / fmaxf(sqrtf(ss), 1e-12f);
    if (lane == 0) g_wscale[c] = sc;
    __nv_bfloat16* dst = g_wbf + (size_t)c * DD;
    #pragma unroll
    for (int q = 0; q < 4; q++) {
        __nv_bfloat162 h0 = __floats2bfloat162_rn(v[q].x * sc, v[q].y * sc);
        __nv_bfloat162 h1 = __floats2bfloat162_rn(v[q].z * sc, v[q].w * sc);
        uint2 u;
        u.x = *(uint32_t*)&h0; u.y = *(uint32_t*)&h1;
        *(uint2*)(dst + q * 128 + lane * 4) = u;
    }
}

// ---------------- bf16 mma.sync GEMM + fused exp/sum epilogue ---------------
// Tile 128x256, K=512. A fully resident in SMEM (128KB, staged once).
// B double-buffered 64-K chunks (256x64 bf16 = 32KB each).
// 8 warps (2 m x 4 n), warp tile 64x64, m16n8k16 via ldmatrix.
// SMEM: A 131072 + B 65536 = 196608 bytes dynamic.
#define SMEM_BYTES 196608

__global__ __launch_bounds__(256, 1) void k_gemm() {
    extern __shared__ char smem[];
    __shared__ float red[MBT];
    const uint32_t sA = smem_u32(smem);          // A: [0, 128KB), chunk kc at kc*16384
    const uint32_t sB = sA + 131072;             // B: two 32KB buffers

    const int tid  = threadIdx.x;
    const int lane = tid & 31;
    const int wid  = tid >> 5;
    const int wm   = wid >> 2;                   // 0..1  (m 64-half)
    const int wn   = wid & 3;                    // 0..3  (n 64-quarter)
    const int mBase = blockIdx.x * MBT;
    const int cBase = blockIdx.y * NBT;

    // ---- A prologue staging: 8192 16B segs, swizzled chunk layout ----
    {
        const __nv_bfloat16* asrc = g_xbf + (size_t)mBase * DD;
        #pragma unroll
        for (int s = 0; s < 32; s++) {
            int lin = tid + s * 256;
            int m = lin >> 6;                    // 0..127
            int kseg = lin & 63;                 // 0..63
            int kc = kseg >> 3;
            int col = kseg & 7;
            uint32_t dst = sA + (uint32_t)(kc * 16384 + m * 128 + ((col ^ (m & 7)) << 4));
            CP_ASYNC16(dst, asrc + (size_t)m * DD + kseg * 8);
        }
    }

    // ---- B staging bases: 2048 segs/chunk, 8 per thread ----
    const int b_row0 = tid >> 3;                 // 0..31 (advances by 32 per s)
    const int b_col  = tid & 7;
    uint32_t st_b0 = sB + (uint32_t)(b_row0 * 128 + ((b_col ^ (b_row0 & 7)) << 4));
    const __nv_bfloat16* gp_b[8];
    #pragma unroll
    for (int s = 0; s < 8; s++) {
        int row = b_row0 + s * 32;
        int br = cBase + row; if (br >= CC) br = CC - 1;   // clamp; masked in epilogue
        gp_b[s] = g_wbf + (size_t)br * DD + b_col * 8;
    }

    // ---- stage B chunk 0 + commit with A ----
    #pragma unroll
    for (int s = 0; s < 8; s++) CP_ASYNC16(st_b0 + s * 32 * 128, gp_b[s]);
    CP_COMMIT();

    // ---- ldmatrix per-lane addressing (validated in R8) ----
    const int arow = (lane & 7) + 8 * ((lane >> 3) & 1);
    const int akh  = lane >> 4;
    const int brow = (lane & 7) + 8 * (lane >> 4);
    const int bkh  = (lane >> 3) & 1;
    const int swz  = lane & 7;
    uint32_t aptr[4], bptr[4];
    #pragma unroll
    for (int mi = 0; mi < 4; mi++)
        aptr[mi] = sA + (uint32_t)((wm * 64 + mi * 16 + arow) * 128);
    #pragma unroll
    for (int jp = 0; jp < 4; jp++)
        bptr[jp] = sB + (uint32_t)((wn * 64 + jp * 16 + brow) * 128);

    float d[4][8][4];
    #pragma unroll
    for (int mi = 0; mi < 4; mi++)
        #pragma unroll
        for (int nj = 0; nj < 8; nj++)
            #pragma unroll
            for (int r = 0; r < 4; r++) d[mi][nj][r] = 0.0f;

    for (int kc = 0; kc < NCH; kc++) {
        const uint32_t bufoff = (uint32_t)((kc & 1) * 32768);
        const uint32_t aoff   = (uint32_t)(kc * 16384);
        if (kc + 1 < NCH) {
            const uint32_t nb = (uint32_t)(((kc + 1) & 1) * 32768);
            #pragma unroll
            for (int s = 0; s < 8; s++)
                CP_ASYNC16(st_b0 + nb + s * 32 * 128, gp_b[s] + (kc + 1) * KC);
            CP_COMMIT();
            CP_WAIT(1);                 // chunk kc (and A, at kc=0) has landed
        } else {
            CP_WAIT(0);
        }
        __syncthreads();

        #pragma unroll
        for (int ks = 0; ks < 4; ks++) {
            const uint32_t cA = (uint32_t)(((ks * 2 + akh) ^ swz) << 4);
            const uint32_t cB = (uint32_t)(((ks * 2 + bkh) ^ swz) << 4);
            uint32_t a[4][4], b[4][4];
            #pragma unroll
            for (int mi = 0; mi < 4; mi++) LDSM4(a[mi], aptr[mi] + aoff + cA);
            #pragma unroll
            for (int jp = 0; jp < 4; jp++) LDSM4(b[jp], bptr[jp] + bufoff + cB);
            #pragma unroll
            for (int mi = 0; mi < 4; mi++)
                #pragma unroll
                for (int jp = 0; jp < 4; jp++) {
                    MMA16816(d[mi][2 * jp + 0], a[mi], b[jp][0], b[jp][1]);
                    MMA16816(d[mi][2 * jp + 1], a[mi], b[jp][2], b[jp][3]);
                }
        }
        __syncthreads();                // B buffer safe to overwrite next iter
    }

    // ---- epilogue: logits are d[] directly (scale folded into g_wbf) ----
    if (tid < MBT) red[tid] = 0.0f;
    __syncthreads();

    const int q  = lane & 3;
    const int g4 = lane >> 2;
    #pragma unroll
    for (int mi = 0; mi < 4; mi++) {
        float r0 = 0.0f, r1 = 0.0f;
        #pragma unroll
        for (int nj = 0; nj < 8; nj++) {
            int c0 = cBase + wn * 64 + nj * 8 + q * 2;
            if (c0 < CC)     { r0 += __expf(d[mi][nj][0] - SCALE);
                               r1 += __expf(d[mi][nj][2] - SCALE); }
            if (c0 + 1 < CC) { r0 += __expf(d[mi][nj][1] - SCALE);
                               r1 += __expf(d[mi][nj][3] - SCALE); }
        }
        r0 += __shfl_xor_sync(0xffffffffu, r0, 1);
        r0 += __shfl_xor_sync(0xffffffffu, r0, 2);
        r1 += __shfl_xor_sync(0xffffffffu, r1, 1);
        r1 += __shfl_xor_sync(0xffffffffu, r1, 2);
        if (q == 0) {
            atomicAdd(&red[wm * 64 + mi * 16 + g4],     r0);
            atomicAdd(&red[wm * 64 + mi * 16 + 8 + g4], r1);
        }
    }
    __syncthreads();
    if (tid < MBT) atomicAdd(&g_expsum[mBase + tid], red[tid]);
}

// ---------------- per-row nll (exact fp32 label logit) ----------------------
__global__ void k_nll(const float* __restrict__ w, const void* __restrict__ labv) {
    const int warp = threadIdx.x >> 5;
    const int lane = threadIdx.x & 31;
    const int i = blockIdx.x * 8 + warp;
    long long yi;
    if (g_is64) yi = ((const long long*)labv)[i];
    else        yi = (long long)((const int*)labv)[i];
    const float4* a4 = (const float4*)(g_xn + i * DD);
    const float4* w4 = (const float4*)(w + (size_t)yi * DD);
    float dot = 0.0f;
    #pragma unroll
    for (int qq = 0; qq < 4; qq++) {
        float4 a = a4[qq * 32 + lane];
        float4 b = w4[qq * 32 + lane];
        dot += a.x * b.x + a.y * b.y + a.z * b.z + a.w * b.w;
    }
    #pragma unroll
    for (int o = 16; o > 0; o >>= 1) dot += __shfl_xor_sync(0xffffffffu, dot, o);
    if (lane == 0)
        g_nll[i] = SCALE + logf(g_expsum[i]) - g_wscale[yi] * dot;
}

// ---------------- deterministic final reduce --------------------------------
__global__ void k_reduce(float* __restrict__ out) {
    __shared__ float sm[16];
    const int t = threadIdx.x;
    float v = g_nll[t];
    #pragma unroll
    for (int o = 16; o > 0; o >>= 1) v += __shfl_xor_sync(0xffffffffu, v, o);
    if ((t & 31) == 0) sm[t >> 5] = v;
    __syncthreads();
    if (t < 16) {
        float u = sm[t];
        #pragma unroll
        for (int o = 8; o > 0; o >>= 1) u += __shfl_xor_sync(0x0000ffffu, u, o);
        if (t == 0) out[0] = u * (1.0f / (float)BB);
    }
}

// ---------------- launch -----------------------------------------------------
extern "C" void kernel_launch(void* const* d_in, const int* in_sizes, int n_in,
                              void* d_out, int out_size) {
    (void)out_size;
    const float* x = nullptr;
    const float* w = nullptr;
    const void* lab = nullptr;
    for (int i = 0; i < n_in; i++) {
        if (in_sizes[i] == BB * DD)      x = (const float*)d_in[i];
        else if (in_sizes[i] == CC * DD) w = (const float*)d_in[i];
        else if (in_sizes[i] == BB)      lab = d_in[i];
    }

    cudaFuncSetAttribute(k_gemm, cudaFuncAttributeMaxDynamicSharedMemorySize, SMEM_BYTES);

    k_probe<<<1, 256>>>((const int*)lab);
    k_norm_x<<<BB, 128>>>(x);
    k_norm_w<<<CC / 8, 256>>>(w);
    dim3 g3(BB / MBT, (CC + NBT - 1) / NBT);   // (4, 391): batch-fast for L2 W reuse
    k_gemm<<<g3, 256, SMEM_BYTES>>>();
    k_nll<<<BB / 8, 256>>>(w, lab);
    k_reduce<<<1, BB>>>((float*)d_out);
}

// round 11
// speedup vs baseline: 1.8068x; 1.8068x over previous
#include <cuda_runtime.h>
#include <cuda_bf16.h>
#include <math.h>
#include <stdint.h>

#define BB 512
#define DD 512
#define CC 100000
#define SCALE 64.0f

#define MBT 128          // batch tile
#define NBT 128          // class tile
#define KC  64           // K chunk (128 bytes bf16)
#define NCH (DD / KC)    // 8 chunks

// ---------------- device scratch ----------------
__device__ float          g_xn[BB * DD];          // normalized x fp32 (exact label logit)
__device__ __nv_bfloat16  g_xbf[BB * DD];         // normalized x bf16
__device__ __nv_bfloat16  g_wbf[(size_t)CC * DD]; // W * (64/||w||) bf16
__device__ float          g_wscale[CC];
__device__ float          g_expsum[BB];
__device__ float          g_nll[BB];
__device__ int            g_is64;

// ---------------- PTX helpers (baseline compute_103-safe only) --------------
__device__ __forceinline__ uint32_t smem_u32(const void* p) {
    uint32_t a;
    asm("{ .reg .u64 t; cvta.to.shared.u64 t, %1; cvt.u32.u64 %0, t; }" : "=r"(a) : "l"(p));
    return a;
}
#define CP_ASYNC16(dst, src) \
    asm volatile("cp.async.cg.shared.global [%0], [%1], 16;" :: "r"(dst), "l"(src) : "memory")
#define CP_COMMIT() asm volatile("cp.async.commit_group;" ::: "memory")
#define CP_WAIT(n)  asm volatile("cp.async.wait_group %0;" :: "n"(n) : "memory")

#define LDSM4(r, addr) \
    asm volatile("ldmatrix.sync.aligned.m8n8.x4.shared.b16 {%0,%1,%2,%3}, [%4];" \
        : "=r"((r)[0]), "=r"((r)[1]), "=r"((r)[2]), "=r"((r)[3]) : "r"(addr))

#define MMA16816(d, a, b0v, b1v) \
    asm volatile("mma.sync.aligned.m16n8k16.row.col.f32.bf16.bf16.f32 " \
        "{%0,%1,%2,%3}, {%4,%5,%6,%7}, {%8,%9}, {%0,%1,%2,%3};" \
        : "+f"((d)[0]), "+f"((d)[1]), "+f"((d)[2]), "+f"((d)[3]) \
        : "r"((a)[0]), "r"((a)[1]), "r"((a)[2]), "r"((a)[3]), "r"(b0v), "r"(b1v))

// ---------------- label dtype probe ----------------
__global__ void k_probe(const int* __restrict__ lab) {
    __shared__ int s_any;
    if (threadIdx.x == 0) s_any = 0;
    __syncthreads();
    if (lab[2 * threadIdx.x + 1] != 0) atomicOr(&s_any, 1);
    __syncthreads();
    if (threadIdx.x == 0) g_is64 = (s_any == 0) ? 1 : 0;
}

// ---------------- x normalize: fp32 + bf16 outputs, zero expsum -------------
__global__ void k_norm_x(const float* __restrict__ x) {
    __shared__ float s_part[4];
    __shared__ float s_inv;
    const int m = blockIdx.x;
    const int t = threadIdx.x;                 // 128 threads
    float4 v = ((const float4*)x)[m * 128 + t];
    float ss = v.x * v.x + v.y * v.y + v.z * v.z + v.w * v.w;
    #pragma unroll
    for (int o = 16; o > 0; o >>= 1) ss += __shfl_xor_sync(0xffffffffu, ss, o);
    if ((t & 31) == 0) s_part[t >> 5] = ss;
    __syncthreads();
    if (t == 0) {
        float tot = s_part[0] + s_part[1] + s_part[2] + s_part[3];
        s_inv = 1.0f / fmaxf(sqrtf(tot), 1e-12f);
        g_expsum[m] = 0.0f;                    // re-zeroed every graph replay
    }
    __syncthreads();
    const float inv = s_inv;
    float4 o4 = make_float4(v.x * inv, v.y * inv, v.z * inv, v.w * inv);
    ((float4*)g_xn)[m * 128 + t] = o4;
    __nv_bfloat162 h0 = __floats2bfloat162_rn(o4.x, o4.y);
    __nv_bfloat162 h1 = __floats2bfloat162_rn(o4.z, o4.w);
    uint2 u;
    u.x = *(uint32_t*)&h0; u.y = *(uint32_t*)&h1;
    *(uint2*)(g_xbf + m * DD + t * 4) = u;
}

// ---------------- W norms + scaled bf16 convert (one warp per row) ----------
__global__ void k_norm_w(const float* __restrict__ w) {
    const int c = blockIdx.x * 8 + (threadIdx.x >> 5);
    const int lane = threadIdx.x & 31;
    const float4* w4 = (const float4*)(w + (size_t)c * DD);
    float4 v[4];
    float ss = 0.0f;
    #pragma unroll
    for (int q = 0; q < 4; q++) {
        v[q] = w4[q * 32 + lane];
        ss += v[q].x * v[q].x + v[q].y * v[q].y + v[q].z * v[q].z + v[q].w * v[q].w;
    }
    #pragma unroll
    for (int o = 16; o > 0; o >>= 1) ss += __shfl_xor_sync(0xffffffffu, ss, o);
    const float sc = SCALE / fmaxf(sqrtf(ss), 1e-12f);
    if (lane == 0) g_wscale[c] = sc;
    __nv_bfloat16* dst = g_wbf + (size_t)c * DD;
    #pragma unroll
    for (int q = 0; q < 4; q++) {
        __nv_bfloat162 h0 = __floats2bfloat162_rn(v[q].x * sc, v[q].y * sc);
        __nv_bfloat162 h1 = __floats2bfloat162_rn(v[q].z * sc, v[q].w * sc);
        uint2 u;
        u.x = *(uint32_t*)&h0; u.y = *(uint32_t*)&h1;
        *(uint2*)(dst + q * 128 + lane * 4) = u;
    }
}

// ---------------- bf16 mma.sync GEMM + fused exp/sum epilogue ---------------
// Tile 128x128 (R8 validated), K=512, 8 chunks of 64 double-buffered cp.async.
// 8 warps (2 m x 4 n), warp tile 64x32. __launch_bounds__(256,2) caps regs at
// 128 so TWO CTAs co-reside per SM: second CTA's MMAs cover first's cp.async /
// sync / LDSM latency (R8 showed tensor=45.7% @ occ 12.5%).
// SMEM: A[2][128][64] + B[2][128][64] bf16 = 64KB dynamic per CTA.
#define SMEM_BYTES 65536

__global__ __launch_bounds__(256, 2) void k_gemm() {
    extern __shared__ char smem[];
    __shared__ float red[MBT];
    const uint32_t sA = smem_u32(smem);          // A buffers at [0, 32KB)
    const uint32_t sB = sA + 32768;              // B buffers at [32KB, 64KB)

    const int tid  = threadIdx.x;
    const int lane = tid & 31;
    const int wid  = tid >> 5;
    const int wm   = wid >> 2;                   // 0..1
    const int wn   = wid & 3;                    // 0..3
    const int mBase = blockIdx.x * MBT;
    const int cBase = blockIdx.y * NBT;

    // ---- staging precompute: 1024 16B segs per operand per chunk ----
    // row = (tid + s*256)>>3 advances by 32 per s; col fixed => constant strides
    const int srow = tid >> 3;                   // 0..31
    const int scol = tid & 7;
    const uint32_t st0 = (uint32_t)(srow * 128 + ((scol ^ (srow & 7)) << 4));
    const uint32_t st_a0 = sA + st0;
    const uint32_t st_b0 = sB + st0;
    const __nv_bfloat16* gp_a0 = g_xbf + (size_t)(mBase + srow) * DD + scol * 8;
    const __nv_bfloat16* gp_b[4];
    #pragma unroll
    for (int s = 0; s < 4; s++) {
        int br = cBase + srow + s * 32; if (br >= CC) br = CC - 1; // clamp; masked later
        gp_b[s] = g_wbf + (size_t)br * DD + scol * 8;
    }

    // ---- ldmatrix per-lane addressing (validated in R8) ----
    const int arow = (lane & 7) + 8 * ((lane >> 3) & 1);
    const int akh  = lane >> 4;
    const int brow = (lane & 7) + 8 * (lane >> 4);
    const int bkh  = (lane >> 3) & 1;
    const int swz  = lane & 7;
    uint32_t aptr[4], bptr[2];
    #pragma unroll
    for (int mi = 0; mi < 4; mi++)
        aptr[mi] = sA + (uint32_t)((wm * 64 + mi * 16 + arow) * 128);
    #pragma unroll
    for (int jp = 0; jp < 2; jp++)
        bptr[jp] = sB + (uint32_t)((wn * 32 + jp * 16 + brow) * 128);

    float d[4][4][4];
    #pragma unroll
    for (int mi = 0; mi < 4; mi++)
        #pragma unroll
        for (int nj = 0; nj < 4; nj++)
            #pragma unroll
            for (int r = 0; r < 4; r++) d[mi][nj][r] = 0.0f;

    // ---- prologue: stage chunk 0 into buf 0 ----
    #pragma unroll
    for (int s = 0; s < 4; s++) {
        CP_ASYNC16(st_a0 + s * 4096, gp_a0 + s * 32 * DD);
        CP_ASYNC16(st_b0 + s * 4096, gp_b[s]);
    }
    CP_COMMIT();

    for (int kc = 0; kc < NCH; kc++) {
        const uint32_t bufoff = (uint32_t)((kc & 1) * 16384);
        if (kc + 1 < NCH) {
            const uint32_t nb = (uint32_t)(((kc + 1) & 1) * 16384);
            #pragma unroll
            for (int s = 0; s < 4; s++) {
                CP_ASYNC16(st_a0 + nb + s * 4096, gp_a0 + s * 32 * DD + (kc + 1) * KC);
                CP_ASYNC16(st_b0 + nb + s * 4096, gp_b[s] + (kc + 1) * KC);
            }
            CP_COMMIT();
            CP_WAIT(1);                 // chunk kc has landed
        } else {
            CP_WAIT(0);
        }
        __syncthreads();

        #pragma unroll
        for (int ks = 0; ks < 4; ks++) {
            const uint32_t cA = (uint32_t)(((ks * 2 + akh) ^ swz) << 4);
            const uint32_t cB = (uint32_t)(((ks * 2 + bkh) ^ swz) << 4);
            uint32_t a[4][4], b[2][4];
            #pragma unroll
            for (int mi = 0; mi < 4; mi++) LDSM4(a[mi], aptr[mi] + bufoff + cA);
            #pragma unroll
            for (int jp = 0; jp < 2; jp++) LDSM4(b[jp], bptr[jp] + bufoff + cB);
            #pragma unroll
            for (int mi = 0; mi < 4; mi++) {
                MMA16816(d[mi][0], a[mi], b[0][0], b[0][1]);
                MMA16816(d[mi][1], a[mi], b[0][2], b[0][3]);
                MMA16816(d[mi][2], a[mi], b[1][0], b[1][1]);
                MMA16816(d[mi][3], a[mi], b[1][2], b[1][3]);
            }
        }
        __syncthreads();                // buffer safe to overwrite next iter
    }

    // ---- epilogue: logits are d[] directly (scale folded into g_wbf) ----
    if (tid < MBT) red[tid] = 0.0f;
    __syncthreads();

    const int q  = lane & 3;
    const int g4 = lane >> 2;
    #pragma unroll
    for (int mi = 0; mi < 4; mi++) {
        float r0 = 0.0f, r1 = 0.0f;
        #pragma unroll
        for (int nj = 0; nj < 4; nj++) {
            int c0 = cBase + wn * 32 + nj * 8 + q * 2;
            if (c0 < CC)     { r0 += __expf(d[mi][nj][0] - SCALE);
                               r1 += __expf(d[mi][nj][2] - SCALE); }
            if (c0 + 1 < CC) { r0 += __expf(d[mi][nj][1] - SCALE);
                               r1 += __expf(d[mi][nj][3] - SCALE); }
        }
        r0 += __shfl_xor_sync(0xffffffffu, r0, 1);
        r0 += __shfl_xor_sync(0xffffffffu, r0, 2);
        r1 += __shfl_xor_sync(0xffffffffu, r1, 1);
        r1 += __shfl_xor_sync(0xffffffffu, r1, 2);
        if (q == 0) {
            atomicAdd(&red[wm * 64 + mi * 16 + g4],     r0);
            atomicAdd(&red[wm * 64 + mi * 16 + 8 + g4], r1);
        }
    }
    __syncthreads();
    if (tid < MBT) atomicAdd(&g_expsum[mBase + tid], red[tid]);
}

// ---------------- per-row nll (exact fp32 label logit) ----------------------
__global__ void k_nll(const float* __restrict__ w, const void* __restrict__ labv) {
    const int warp = threadIdx.x >> 5;
    const int lane = threadIdx.x & 31;
    const int i = blockIdx.x * 8 + warp;
    long long yi;
    if (g_is64) yi = ((const long long*)labv)[i];
    else        yi = (long long)((const int*)labv)[i];
    const float4* a4 = (const float4*)(g_xn + i * DD);
    const float4* w4 = (const float4*)(w + (size_t)yi * DD);
    float dot = 0.0f;
    #pragma unroll
    for (int qq = 0; qq < 4; qq++) {
        float4 a = a4[qq * 32 + lane];
        float4 b = w4[qq * 32 + lane];
        dot += a.x * b.x + a.y * b.y + a.z * b.z + a.w * b.w;
    }
    #pragma unroll
    for (int o = 16; o > 0; o >>= 1) dot += __shfl_xor_sync(0xffffffffu, dot, o);
    if (lane == 0)
        g_nll[i] = SCALE + logf(g_expsum[i]) - g_wscale[yi] * dot;
}

// ---------------- deterministic final reduce --------------------------------
__global__ void k_reduce(float* __restrict__ out) {
    __shared__ float sm[16];
    const int t = threadIdx.x;
    float v = g_nll[t];
    #pragma unroll
    for (int o = 16; o > 0; o >>= 1) v += __shfl_xor_sync(0xffffffffu, v, o);
    if ((t & 31) == 0) sm[t >> 5] = v;
    __syncthreads();
    if (t < 16) {
        float u = sm[t];
        #pragma unroll
        for (int o = 8; o > 0; o >>= 1) u += __shfl_xor_sync(0x0000ffffu, u, o);
        if (t == 0) out[0] = u * (1.0f / (float)BB);
    }
}

// ---------------- launch -----------------------------------------------------
extern "C" void kernel_launch(void* const* d_in, const int* in_sizes, int n_in,
                              void* d_out, int out_size) {
    (void)out_size;
    const float* x = nullptr;
    const float* w = nullptr;
    const void* lab = nullptr;
    for (int i = 0; i < n_in; i++) {
        if (in_sizes[i] == BB * DD)      x = (const float*)d_in[i];
        else if (in_sizes[i] == CC * DD) w = (const float*)d_in[i];
        else if (in_sizes[i] == BB)      lab = d_in[i];
    }

    cudaFuncSetAttribute(k_gemm, cudaFuncAttributeMaxDynamicSharedMemorySize, SMEM_BYTES);

    k_probe<<<1, 256>>>((const int*)lab);
    k_norm_x<<<BB, 128>>>(x);
    k_norm_w<<<CC / 8, 256>>>(w);
    dim3 g3(BB / MBT, (CC + NBT - 1) / NBT);   // (4, 782): batch-fast for L2 W reuse
    k_gemm<<<g3, 256, SMEM_BYTES>>>();
    k_nll<<<BB / 8, 256>>>(w, lab);
    k_reduce<<<1, BB>>>((float*)d_out);
}

// round 12
// speedup vs baseline: 1.8100x; 1.0018x over previous
#include <cuda_runtime.h>
#include <cuda_bf16.h>
#include <math.h>
#include <stdint.h>

#define BB 512
#define DD 512
#define CC 100000
#define SCALE 64.0f

#define MBT 128          // batch tile
#define NBT 128          // class tile
#define KC  64           // K chunk (128 bytes bf16)
#define NCH (DD / KC)    // 8 chunks
#define NST 3            // cp.async pipeline stages

// ---------------- device scratch ----------------
__device__ float          g_xn[BB * DD];          // normalized x fp32 (exact label logit)
__device__ __nv_bfloat16  g_xbf[BB * DD];         // normalized x bf16
__device__ __nv_bfloat16  g_wbf[(size_t)CC * DD]; // W * (64/||w||) bf16
__device__ float          g_wscale[CC];
__device__ float          g_expsum[BB];
__device__ float          g_nll[BB];
__device__ int            g_is64;

// ---------------- PTX helpers (baseline compute_103-safe only) --------------
__device__ __forceinline__ uint32_t smem_u32(const void* p) {
    uint32_t a;
    asm("{ .reg .u64 t; cvta.to.shared.u64 t, %1; cvt.u32.u64 %0, t; }" : "=r"(a) : "l"(p));
    return a;
}
#define CP_ASYNC16(dst, src) \
    asm volatile("cp.async.cg.shared.global [%0], [%1], 16;" :: "r"(dst), "l"(src) : "memory")
#define CP_COMMIT() asm volatile("cp.async.commit_group;" ::: "memory")
#define CP_WAIT(n)  asm volatile("cp.async.wait_group %0;" :: "n"(n) : "memory")

#define LDSM4(r, addr) \
    asm volatile("ldmatrix.sync.aligned.m8n8.x4.shared.b16 {%0,%1,%2,%3}, [%4];" \
        : "=r"((r)[0]), "=r"((r)[1]), "=r"((r)[2]), "=r"((r)[3]) : "r"(addr))

#define MMA16816(d, a, b0v, b1v) \
    asm volatile("mma.sync.aligned.m16n8k16.row.col.f32.bf16.bf16.f32 " \
        "{%0,%1,%2,%3}, {%4,%5,%6,%7}, {%8,%9}, {%0,%1,%2,%3};" \
        : "+f"((d)[0]), "+f"((d)[1]), "+f"((d)[2]), "+f"((d)[3]) \
        : "r"((a)[0]), "r"((a)[1]), "r"((a)[2]), "r"((a)[3]), "r"(b0v), "r"(b1v))

// ---------------- label dtype probe ----------------
__global__ void k_probe(const int* __restrict__ lab) {
    __shared__ int s_any;
    if (threadIdx.x == 0) s_any = 0;
    __syncthreads();
    if (lab[2 * threadIdx.x + 1] != 0) atomicOr(&s_any, 1);
    __syncthreads();
    if (threadIdx.x == 0) g_is64 = (s_any == 0) ? 1 : 0;
}

// ---------------- x normalize: fp32 + bf16 outputs, zero expsum -------------
__global__ void k_norm_x(const float* __restrict__ x) {
    __shared__ float s_part[4];
    __shared__ float s_inv;
    const int m = blockIdx.x;
    const int t = threadIdx.x;                 // 128 threads
    float4 v = ((const float4*)x)[m * 128 + t];
    float ss = v.x * v.x + v.y * v.y + v.z * v.z + v.w * v.w;
    #pragma unroll
    for (int o = 16; o > 0; o >>= 1) ss += __shfl_xor_sync(0xffffffffu, ss, o);
    if ((t & 31) == 0) s_part[t >> 5] = ss;
    __syncthreads();
    if (t == 0) {
        float tot = s_part[0] + s_part[1] + s_part[2] + s_part[3];
        s_inv = 1.0f / fmaxf(sqrtf(tot), 1e-12f);
        g_expsum[m] = 0.0f;                    // re-zeroed every graph replay
    }
    __syncthreads();
    const float inv = s_inv;
    float4 o4 = make_float4(v.x * inv, v.y * inv, v.z * inv, v.w * inv);
    ((float4*)g_xn)[m * 128 + t] = o4;
    __nv_bfloat162 h0 = __floats2bfloat162_rn(o4.x, o4.y);
    __nv_bfloat162 h1 = __floats2bfloat162_rn(o4.z, o4.w);
    uint2 u;
    u.x = *(uint32_t*)&h0; u.y = *(uint32_t*)&h1;
    *(uint2*)(g_xbf + m * DD + t * 4) = u;
}

// ---------------- W norms + scaled bf16 convert (one warp per row) ----------
__global__ void k_norm_w(const float* __restrict__ w) {
    const int c = blockIdx.x * 8 + (threadIdx.x >> 5);
    const int lane = threadIdx.x & 31;
    const float4* w4 = (const float4*)(w + (size_t)c * DD);
    float4 v[4];
    float ss = 0.0f;
    #pragma unroll
    for (int q = 0; q < 4; q++) {
        v[q] = w4[q * 32 + lane];
        ss += v[q].x * v[q].x + v[q].y * v[q].y + v[q].z * v[q].z + v[q].w * v[q].w;
    }
    #pragma unroll
    for (int o = 16; o > 0; o >>= 1) ss += __shfl_xor_sync(0xffffffffu, ss, o);
    const float sc = SCALE / fmaxf(sqrtf(ss), 1e-12f);
    if (lane == 0) g_wscale[c] = sc;
    __nv_bfloat16* dst = g_wbf + (size_t)c * DD;
    #pragma unroll
    for (int q = 0; q < 4; q++) {
        __nv_bfloat162 h0 = __floats2bfloat162_rn(v[q].x * sc, v[q].y * sc);
        __nv_bfloat162 h1 = __floats2bfloat162_rn(v[q].z * sc, v[q].w * sc);
        uint2 u;
        u.x = *(uint32_t*)&h0; u.y = *(uint32_t*)&h1;
        *(uint2*)(dst + q * 128 + lane * 4) = u;
    }
}

// ---------------- bf16 mma.sync GEMM + fused exp/sum epilogue ---------------
// Tile 128x128, K=512. 3-stage cp.async ring (A[3]+B[3] = 96KB), ONE
// __syncthreads per chunk; 2 CTAs/SM via __launch_bounds__(256,2).
// 8 warps (2 m x 4 n), warp tile 64x32, m16n8k16 via ldmatrix.
#define SMEM_BYTES (NST * 32768)   // 98304: 3 stages x (A 16KB + B 16KB)

__global__ __launch_bounds__(256, 2) void k_gemm() {
    extern __shared__ char smem[];
    __shared__ float red[MBT];
    const uint32_t sA = smem_u32(smem);          // stage s: A at s*16384
    const uint32_t sB = sA + NST * 16384;        // stage s: B at s*16384

    const int tid  = threadIdx.x;
    const int lane = tid & 31;
    const int wid  = tid >> 5;
    const int wm   = wid >> 2;                   // 0..1
    const int wn   = wid & 3;                    // 0..3
    const int mBase = blockIdx.x * MBT;
    const int cBase = blockIdx.y * NBT;

    // ---- staging precompute: 1024 16B segs per operand per chunk ----
    const int srow = tid >> 3;                   // 0..31
    const int scol = tid & 7;
    const uint32_t st0 = (uint32_t)(srow * 128 + ((scol ^ (srow & 7)) << 4));
    const uint32_t st_a0 = sA + st0;
    const uint32_t st_b0 = sB + st0;
    const __nv_bfloat16* gp_a0 = g_xbf + (size_t)(mBase + srow) * DD + scol * 8;
    const __nv_bfloat16* gp_b[4];
    #pragma unroll
    for (int s = 0; s < 4; s++) {
        int br = cBase + srow + s * 32; if (br >= CC) br = CC - 1; // clamp; masked later
        gp_b[s] = g_wbf + (size_t)br * DD + scol * 8;
    }

    // ---- ldmatrix per-lane addressing (validated in R8) ----
    const int arow = (lane & 7) + 8 * ((lane >> 3) & 1);
    const int akh  = lane >> 4;
    const int brow = (lane & 7) + 8 * (lane >> 4);
    const int bkh  = (lane >> 3) & 1;
    const int swz  = lane & 7;
    uint32_t aptr[4], bptr[2];
    #pragma unroll
    for (int mi = 0; mi < 4; mi++)
        aptr[mi] = sA + (uint32_t)((wm * 64 + mi * 16 + arow) * 128);
    #pragma unroll
    for (int jp = 0; jp < 2; jp++)
        bptr[jp] = sB + (uint32_t)((wn * 32 + jp * 16 + brow) * 128);

    float d[4][4][4];
    #pragma unroll
    for (int mi = 0; mi < 4; mi++)
        #pragma unroll
        for (int nj = 0; nj < 4; nj++)
            #pragma unroll
            for (int r = 0; r < 4; r++) d[mi][nj][r] = 0.0f;

    // ---- prologue: stage chunks 0,1 into bufs 0,1 ----
    #pragma unroll
    for (int p = 0; p < 2; p++) {
        const uint32_t bo = (uint32_t)(p * 16384);
        #pragma unroll
        for (int s = 0; s < 4; s++) {
            CP_ASYNC16(st_a0 + bo + s * 4096, gp_a0 + s * 32 * DD + p * KC);
            CP_ASYNC16(st_b0 + bo + s * 4096, gp_b[s] + p * KC);
        }
        CP_COMMIT();
    }

    int bufc = 0;                                // kc % 3
    for (int kc = 0; kc < NCH; kc++) {
        if (kc + 1 < NCH) CP_WAIT(1); else CP_WAIT(0);
        __syncthreads();                         // chunk kc landed; buf (kc-1)%3 free
        if (kc + 2 < NCH) {
            int bufn = bufc - 1; if (bufn < 0) bufn += NST;   // (kc+2) % 3
            const uint32_t nb = (uint32_t)(bufn * 16384);
            #pragma unroll
            for (int s = 0; s < 4; s++) {
                CP_ASYNC16(st_a0 + nb + s * 4096, gp_a0 + s * 32 * DD + (kc + 2) * KC);
                CP_ASYNC16(st_b0 + nb + s * 4096, gp_b[s] + (kc + 2) * KC);
            }
            CP_COMMIT();
        }

        const uint32_t bufoff = (uint32_t)(bufc * 16384);
        #pragma unroll
        for (int ks = 0; ks < 4; ks++) {
            const uint32_t cA = (uint32_t)(((ks * 2 + akh) ^ swz) << 4);
            const uint32_t cB = (uint32_t)(((ks * 2 + bkh) ^ swz) << 4);
            uint32_t a[4][4], b[2][4];
            #pragma unroll
            for (int mi = 0; mi < 4; mi++) LDSM4(a[mi], aptr[mi] + bufoff + cA);
            #pragma unroll
            for (int jp = 0; jp < 2; jp++) LDSM4(b[jp], bptr[jp] + bufoff + cB);
            #pragma unroll
            for (int mi = 0; mi < 4; mi++) {
                MMA16816(d[mi][0], a[mi], b[0][0], b[0][1]);
                MMA16816(d[mi][1], a[mi], b[0][2], b[0][3]);
                MMA16816(d[mi][2], a[mi], b[1][0], b[1][1]);
                MMA16816(d[mi][3], a[mi], b[1][2], b[1][3]);
            }
        }
        if (++bufc == NST) bufc = 0;
    }

    // ---- epilogue: logits are d[] directly (scale folded into g_wbf) ----
    if (tid < MBT) red[tid] = 0.0f;
    __syncthreads();

    const int q  = lane & 3;
    const int g4 = lane >> 2;
    #pragma unroll
    for (int mi = 0; mi < 4; mi++) {
        float r0 = 0.0f, r1 = 0.0f;
        #pragma unroll
        for (int nj = 0; nj < 4; nj++) {
            int c0 = cBase + wn * 32 + nj * 8 + q * 2;
            if (c0 < CC)     { r0 += __expf(d[mi][nj][0] - SCALE);
                               r1 += __expf(d[mi][nj][2] - SCALE); }
            if (c0 + 1 < CC) { r0 += __expf(d[mi][nj][1] - SCALE);
                               r1 += __expf(d[mi][nj][3] - SCALE); }
        }
        r0 += __shfl_xor_sync(0xffffffffu, r0, 1);
        r0 += __shfl_xor_sync(0xffffffffu, r0, 2);
        r1 += __shfl_xor_sync(0xffffffffu, r1, 1);
        r1 += __shfl_xor_sync(0xffffffffu, r1, 2);
        if (q == 0) {
            atomicAdd(&red[wm * 64 + mi * 16 + g4],     r0);
            atomicAdd(&red[wm * 64 + mi * 16 + 8 + g4], r1);
        }
    }
    __syncthreads();
    if (tid < MBT) atomicAdd(&g_expsum[mBase + tid], red[tid]);
}

// ---------------- per-row nll (exact fp32 label logit) ----------------------
__global__ void k_nll(const float* __restrict__ w, const void* __restrict__ labv) {
    const int warp = threadIdx.x >> 5;
    const int lane = threadIdx.x & 31;
    const int i = blockIdx.x * 8 + warp;
    long long yi;
    if (g_is64) yi = ((const long long*)labv)[i];
    else        yi = (long long)((const int*)labv)[i];
    const float4* a4 = (const float4*)(g_xn + i * DD);
    const float4* w4 = (const float4*)(w + (size_t)yi * DD);
    float dot = 0.0f;
    #pragma unroll
    for (int qq = 0; qq < 4; qq++) {
        float4 a = a4[qq * 32 + lane];
        float4 b = w4[qq * 32 + lane];
        dot += a.x * b.x + a.y * b.y + a.z * b.z + a.w * b.w;
    }
    #pragma unroll
    for (int o = 16; o > 0; o >>= 1) dot += __shfl_xor_sync(0xffffffffu, dot, o);
    if (lane == 0)
        g_nll[i] = SCALE + logf(g_expsum[i]) - g_wscale[yi] * dot;
}

// ---------------- deterministic final reduce --------------------------------
__global__ void k_reduce(float* __restrict__ out) {
    __shared__ float sm[16];
    const int t = threadIdx.x;
    float v = g_nll[t];
    #pragma unroll
    for (int o = 16; o > 0; o >>= 1) v += __shfl_xor_sync(0xffffffffu, v, o);
    if ((t & 31) == 0) sm[t >> 5] = v;
    __syncthreads();
    if (t < 16) {
        float u = sm[t];
        #pragma unroll
        for (int o = 8; o > 0; o >>= 1) u += __shfl_xor_sync(0x0000ffffu, u, o);
        if (t == 0) out[0] = u * (1.0f / (float)BB);
    }
}

// ---------------- launch -----------------------------------------------------
extern "C" void kernel_launch(void* const* d_in, const int* in_sizes, int n_in,
                              void* d_out, int out_size) {
    (void)out_size;
    const float* x = nullptr;
    const float* w = nullptr;
    const void* lab = nullptr;
    for (int i = 0; i < n_in; i++) {
        if (in_sizes[i] == BB * DD)      x = (const float*)d_in[i];
        else if (in_sizes[i] == CC * DD) w = (const float*)d_in[i];
        else if (in_sizes[i] == BB)      lab = d_in[i];
    }

    cudaFuncSetAttribute(k_gemm, cudaFuncAttributeMaxDynamicSharedMemorySize, SMEM_BYTES);

    k_probe<<<1, 256>>>((const int*)lab);
    k_norm_x<<<BB, 128>>>(x);
    k_norm_w<<<CC / 8, 256>>>(w);
    dim3 g3(BB / MBT, (CC + NBT - 1) / NBT);   // (4, 782): batch-fast for L2 W reuse
    k_gemm<<<g3, 256, SMEM_BYTES>>>();
    k_nll<<<BB / 8, 256>>>(w, lab);
    k_reduce<<<1, BB>>>((float*)d_out);
}